// round 1
// baseline (speedup 1.0000x reference)
#include <cuda_runtime.h>

#define BN   8192
#define DIM  128
#define TOPK 128
#define GBLK 128
#define GKC  32

// Scratch (device globals: allocation-free per harness rules)
__device__ float        g_fn[(size_t)BN * DIM];      // normalized feats
__device__ float        g_S[(size_t)BN * BN];        // Gram matrix (256 MB)
__device__ unsigned char g_lab[BN];                  // labels compressed to u8
__device__ float        g_partial[BN];               // per-row topsum - same_sum

// ---- monotonic float<->uint key (descending select works on raw uint order) ----
__device__ __forceinline__ unsigned fkey(float x) {
    unsigned u = __float_as_uint(x);
    return (u & 0x80000000u) ? ~u : (u | 0x80000000u);
}
__device__ __forceinline__ float fval(unsigned k) {
    return __uint_as_float((k & 0x80000000u) ? (k ^ 0x80000000u) : ~k);
}

// ============================ normalize rows ============================
__global__ void normalize_kernel(const float* __restrict__ feats) {
    int w    = (blockIdx.x * blockDim.x + threadIdx.x) >> 5;  // one warp per row
    int lane = threadIdx.x & 31;
    if (w >= BN) return;
    float4 v = ((const float4*)(feats + (size_t)w * DIM))[lane];
    float ss = v.x * v.x + v.y * v.y + v.z * v.z + v.w * v.w;
    #pragma unroll
    for (int o = 16; o; o >>= 1) ss += __shfl_xor_sync(0xffffffffu, ss, o);
    float inv = rsqrtf(ss);
    v.x *= inv; v.y *= inv; v.z *= inv; v.w *= inv;
    ((float4*)(g_fn + (size_t)w * DIM))[lane] = v;
}

// ============================ labels -> u8 (int64 OR int32 tolerant) ============================
// If buffer is int64 little-endian with values in [0,200), all odd 32-bit words are 0.
// Only touches the first 8192 words (safe for both dtypes).
__global__ void label_kernel(const unsigned int* __restrict__ words) {
    int tid = threadIdx.x;
    int any = 0;
    for (int i = tid; i < BN / 2; i += blockDim.x) any |= (words[2 * i + 1] != 0u);
    int tot  = __syncthreads_or(any);
    int is64 = (tot == 0);
    for (int i = tid; i < BN; i += blockDim.x)
        g_lab[i] = (unsigned char)(is64 ? words[2 * i] : words[i]);
}

// ============================ fp32 Gram GEMM, symmetric-half ============================
__global__ void __launch_bounds__(256) gemm_kernel() {
    int bx = blockIdx.x, by = blockIdx.y;
    if (by < bx) return;  // upper triangle only; mirror on write

    __shared__ float As[GKC][GBLK + 4];  // k-major, +4 pad keeps float4 alignment
    __shared__ float Bs[GKC][GBLK + 4];

    int tid = threadIdx.x;
    int tx = tid & 15, ty = tid >> 4;

    float acc[8][8];
    #pragma unroll
    for (int i = 0; i < 8; i++)
        #pragma unroll
        for (int j = 0; j < 8; j++) acc[i][j] = 0.f;

    const float* Ag = g_fn + (size_t)bx * GBLK * DIM;
    const float* Bg = g_fn + (size_t)by * GBLK * DIM;

    for (int k0 = 0; k0 < DIM; k0 += GKC) {
        // load 128 rows x 32 k, transposing to k-major smem
        #pragma unroll
        for (int l = 0; l < 4; l++) {
            int idx = tid + l * 256;          // 0..1023
            int r   = idx >> 3;               // 0..127
            int kv  = idx & 7;                // float4 index within chunk
            float4 va = *(const float4*)(Ag + (size_t)r * DIM + k0 + kv * 4);
            float4 vb = *(const float4*)(Bg + (size_t)r * DIM + k0 + kv * 4);
            As[kv * 4 + 0][r] = va.x; As[kv * 4 + 1][r] = va.y;
            As[kv * 4 + 2][r] = va.z; As[kv * 4 + 3][r] = va.w;
            Bs[kv * 4 + 0][r] = vb.x; Bs[kv * 4 + 1][r] = vb.y;
            Bs[kv * 4 + 2][r] = vb.z; Bs[kv * 4 + 3][r] = vb.w;
        }
        __syncthreads();
        #pragma unroll
        for (int k = 0; k < GKC; k++) {
            float4 a0 = *(const float4*)&As[k][ty * 8];
            float4 a1 = *(const float4*)&As[k][ty * 8 + 4];
            float4 b0 = *(const float4*)&Bs[k][tx * 8];
            float4 b1 = *(const float4*)&Bs[k][tx * 8 + 4];
            float a[8] = {a0.x, a0.y, a0.z, a0.w, a1.x, a1.y, a1.z, a1.w};
            float b[8] = {b0.x, b0.y, b0.z, b0.w, b1.x, b1.y, b1.z, b1.w};
            #pragma unroll
            for (int i = 0; i < 8; i++)
                #pragma unroll
                for (int j = 0; j < 8; j++) acc[i][j] += a[i] * b[j];
        }
        __syncthreads();
    }

    // direct tile
    #pragma unroll
    for (int i = 0; i < 8; i++) {
        size_t row = (size_t)(bx * GBLK + ty * 8 + i);
        float* dst = g_S + row * BN + by * GBLK + tx * 8;
        *(float4*)(dst)     = make_float4(acc[i][0], acc[i][1], acc[i][2], acc[i][3]);
        *(float4*)(dst + 4) = make_float4(acc[i][4], acc[i][5], acc[i][6], acc[i][7]);
    }
    // mirrored tile
    if (bx != by) {
        #pragma unroll
        for (int j = 0; j < 8; j++) {
            size_t row = (size_t)(by * GBLK + tx * 8 + j);
            float* dst = g_S + row * BN + bx * GBLK + ty * 8;
            *(float4*)(dst)     = make_float4(acc[0][j], acc[1][j], acc[2][j], acc[3][j]);
            *(float4*)(dst + 4) = make_float4(acc[4][j], acc[5][j], acc[6][j], acc[7][j]);
        }
    }
}

// ============================ per-row top-K sum + same-label sum ============================
__global__ void __launch_bounds__(256) topk_kernel() {
    __shared__ float         vals[BN];      // 32 KB: full similarity row
    __shared__ unsigned char lab[BN];       // 8 KB
    __shared__ unsigned int  hist[256];
    __shared__ float2        red2[256];
    __shared__ int           s_sel, s_above;

    int r   = blockIdx.x;
    int tid = threadIdx.x;

    const float4* Srow = (const float4*)(g_S + (size_t)r * BN);
    for (int i = tid; i < BN / 4; i += 256) ((float4*)vals)[i] = Srow[i];
    for (int i = tid; i < BN; i += 256) lab[i] = g_lab[i];
    __syncthreads();

    unsigned char myl = lab[r];
    if (tid == 0) vals[r] = -1e9f;   // mask self for selection
    __syncthreads();

    // same-label sum (diag excluded explicitly)
    float ssum = 0.f;
    for (int j = tid; j < BN; j += 256)
        if (j != r && lab[j] == myl) ssum += vals[j];

    // exact radix-select of the K-th largest key, 4 passes of 8 bits
    unsigned pref = 0, prefmask = 0;
    int remaining = TOPK;
    int lane = tid & 31;
    for (int shift = 24; shift >= 0; shift -= 8) {
        hist[tid] = 0;
        __syncthreads();
        for (int j = tid; j < BN; j += 256) {
            unsigned k = fkey(vals[j]);
            int bucket = ((k & prefmask) == pref) ? (int)((k >> shift) & 255u) : -1;
            unsigned m = __match_any_sync(0xffffffffu, bucket);  // aggregate to dodge ATOMS serialization
            if (bucket >= 0 && lane == (__ffs(m) - 1))
                atomicAdd(&hist[bucket], (unsigned)__popc(m));
        }
        __syncthreads();
        if (tid == 0) {
            int cum = 0, sel = 0, above = 0;
            for (int b = 255; b >= 0; b--) {
                int c = (int)hist[b];
                if (cum + c >= remaining) { sel = b; above = cum; break; }
                cum += c;
            }
            s_sel = sel; s_above = above;
        }
        __syncthreads();
        pref     |= ((unsigned)s_sel) << shift;
        prefmask |= 0xFFu << shift;
        remaining -= s_above;
        __syncthreads();
    }
    // pref == exact key of K-th largest; (TOPK - remaining) strictly-greater elems
    float tsum = 0.f;
    for (int j = tid; j < BN; j += 256) {
        float v = vals[j];
        if (fkey(v) > pref) tsum += v;
    }

    red2[tid] = make_float2(tsum, ssum);
    __syncthreads();
    for (int s = 128; s > 0; s >>= 1) {
        if (tid < s) {
            red2[tid].x += red2[tid + s].x;
            red2[tid].y += red2[tid + s].y;
        }
        __syncthreads();
    }
    if (tid == 0) {
        float tval = fval(pref);                       // value of threshold key (ties exact)
        g_partial[r] = red2[0].x + (float)remaining * tval - red2[0].y;
    }
}

// ============================ final scalar reduce ============================
__global__ void reduce_kernel(float* __restrict__ out) {
    __shared__ double red[256];
    int tid = threadIdx.x;
    double s = 0.0;
    for (int i = tid; i < BN; i += 256) s += (double)g_partial[i];
    red[tid] = s;
    __syncthreads();
    for (int st = 128; st > 0; st >>= 1) {
        if (tid < st) red[tid] += red[tid + st];
        __syncthreads();
    }
    if (tid == 0) out[0] = (float)(red[0] / (double)BN);
}

// ============================ launch ============================
extern "C" void kernel_launch(void* const* d_in, const int* in_sizes, int n_in,
                              void* d_out, int out_size) {
    (void)in_sizes; (void)n_in; (void)out_size;
    const float*        feats = (const float*)d_in[0];
    const unsigned int* labw  = (const unsigned int*)d_in[1];
    float*              out   = (float*)d_out;

    normalize_kernel<<<BN / 8, 256>>>(feats);   // 8 warps (rows) per block
    label_kernel<<<1, 256>>>(labw);
    dim3 g(BN / GBLK, BN / GBLK);
    gemm_kernel<<<g, 256>>>();
    topk_kernel<<<BN, 256>>>();
    reduce_kernel<<<1, 256>>>(out);
}

// round 2
// speedup vs baseline: 1.5700x; 1.5700x over previous
#include <cuda_runtime.h>

#define BN   8192
#define DIM  128
#define TOPK 128
#define GBLK 128
#define GKC  32

#define NTH      512      // threads per topk block
#define NBKT     1024     // linear histogram buckets over [-1, 1]
#define CAND_MAX 2048     // max in-threshold-bucket candidates (expected ~7)

// Scratch (device globals: allocation-free per harness rules)
__device__ float         g_fn[(size_t)BN * DIM];   // normalized feats
__device__ float         g_S[(size_t)BN * BN];     // Gram matrix (256 MB)
__device__ unsigned char g_lab[BN];                // labels compressed to u8
__device__ float         g_partial[BN];            // per-row topsum - same_sum

// ---- monotonic float<->uint key ----
__device__ __forceinline__ unsigned fkey(float x) {
    unsigned u = __float_as_uint(x);
    return (u & 0x80000000u) ? ~u : (u | 0x80000000u);
}
__device__ __forceinline__ float fval(unsigned k) {
    return __uint_as_float((k & 0x80000000u) ? (k ^ 0x80000000u) : ~k);
}
// monotone linear bucket over [-1, 1] (identical expression everywhere => exact consistency)
__device__ __forceinline__ int bucket_of(float v) {
    int b = (int)fmaf(v, 512.f, 512.f);
    return max(0, min(NBKT - 1, b));
}

// ============================ normalize rows ============================
__global__ void normalize_kernel(const float* __restrict__ feats) {
    int w    = (blockIdx.x * blockDim.x + threadIdx.x) >> 5;
    int lane = threadIdx.x & 31;
    if (w >= BN) return;
    float4 v = ((const float4*)(feats + (size_t)w * DIM))[lane];
    float ss = v.x * v.x + v.y * v.y + v.z * v.z + v.w * v.w;
    #pragma unroll
    for (int o = 16; o; o >>= 1) ss += __shfl_xor_sync(0xffffffffu, ss, o);
    float inv = rsqrtf(ss);
    v.x *= inv; v.y *= inv; v.z *= inv; v.w *= inv;
    ((float4*)(g_fn + (size_t)w * DIM))[lane] = v;
}

// ============================ labels -> u8 (int64 OR int32 tolerant) ============================
__global__ void label_kernel(const unsigned int* __restrict__ words) {
    int tid = threadIdx.x;
    int any = 0;
    for (int i = tid; i < BN / 2; i += blockDim.x) any |= (words[2 * i + 1] != 0u);
    int tot  = __syncthreads_or(any);
    int is64 = (tot == 0);
    for (int i = tid; i < BN; i += blockDim.x)
        g_lab[i] = (unsigned char)(is64 ? words[2 * i] : words[i]);
}

// ============================ fp32 Gram GEMM, symmetric-half ============================
__global__ void __launch_bounds__(256) gemm_kernel() {
    int bx = blockIdx.x, by = blockIdx.y;
    if (by < bx) return;

    __shared__ float As[GKC][GBLK + 4];
    __shared__ float Bs[GKC][GBLK + 4];

    int tid = threadIdx.x;
    int tx = tid & 15, ty = tid >> 4;

    float acc[8][8];
    #pragma unroll
    for (int i = 0; i < 8; i++)
        #pragma unroll
        for (int j = 0; j < 8; j++) acc[i][j] = 0.f;

    const float* Ag = g_fn + (size_t)bx * GBLK * DIM;
    const float* Bg = g_fn + (size_t)by * GBLK * DIM;

    for (int k0 = 0; k0 < DIM; k0 += GKC) {
        #pragma unroll
        for (int l = 0; l < 4; l++) {
            int idx = tid + l * 256;
            int r   = idx >> 3;
            int kv  = idx & 7;
            float4 va = *(const float4*)(Ag + (size_t)r * DIM + k0 + kv * 4);
            float4 vb = *(const float4*)(Bg + (size_t)r * DIM + k0 + kv * 4);
            As[kv * 4 + 0][r] = va.x; As[kv * 4 + 1][r] = va.y;
            As[kv * 4 + 2][r] = va.z; As[kv * 4 + 3][r] = va.w;
            Bs[kv * 4 + 0][r] = vb.x; Bs[kv * 4 + 1][r] = vb.y;
            Bs[kv * 4 + 2][r] = vb.z; Bs[kv * 4 + 3][r] = vb.w;
        }
        __syncthreads();
        #pragma unroll
        for (int k = 0; k < GKC; k++) {
            float4 a0 = *(const float4*)&As[k][ty * 8];
            float4 a1 = *(const float4*)&As[k][ty * 8 + 4];
            float4 b0 = *(const float4*)&Bs[k][tx * 8];
            float4 b1 = *(const float4*)&Bs[k][tx * 8 + 4];
            float a[8] = {a0.x, a0.y, a0.z, a0.w, a1.x, a1.y, a1.z, a1.w};
            float b[8] = {b0.x, b0.y, b0.z, b0.w, b1.x, b1.y, b1.z, b1.w};
            #pragma unroll
            for (int i = 0; i < 8; i++)
                #pragma unroll
                for (int j = 0; j < 8; j++) acc[i][j] += a[i] * b[j];
        }
        __syncthreads();
    }

    #pragma unroll
    for (int i = 0; i < 8; i++) {
        size_t row = (size_t)(bx * GBLK + ty * 8 + i);
        float* dst = g_S + row * BN + by * GBLK + tx * 8;
        *(float4*)(dst)     = make_float4(acc[i][0], acc[i][1], acc[i][2], acc[i][3]);
        *(float4*)(dst + 4) = make_float4(acc[i][4], acc[i][5], acc[i][6], acc[i][7]);
    }
    if (bx != by) {
        #pragma unroll
        for (int j = 0; j < 8; j++) {
            size_t row = (size_t)(by * GBLK + tx * 8 + j);
            float* dst = g_S + row * BN + bx * GBLK + ty * 8;
            *(float4*)(dst)     = make_float4(acc[0][j], acc[1][j], acc[2][j], acc[3][j]);
            *(float4*)(dst + 4) = make_float4(acc[4][j], acc[5][j], acc[6][j], acc[7][j]);
        }
    }
}

// ============================ per-row top-K sum + same-label sum ============================
// Pass 1: load row -> smem, 1024-bucket linear histogram + same-label sum.
// Warp-select bucket containing K-th largest. Pass 2: sum above-bucket + gather
// in-bucket candidates. Mini fkey-radix over candidates -> exact threshold key.
// Pass 3: sum strictly-above-threshold within bucket. Ties via remaining*fval(pref).
__global__ void __launch_bounds__(NTH) topk_kernel() {
    __shared__ float    vals[BN];          // 32 KB
    __shared__ unsigned hist[NBKT];        // 4 KB (low 256 reused by mini-radix)
    __shared__ float    cand[CAND_MAX];    // 8 KB
    __shared__ float    wredA[NTH / 32], wredB[NTH / 32];
    __shared__ int      s_bsel, s_above, s_ncand, s_sel2, s_above2;

    int r    = blockIdx.x;
    int tid  = threadIdx.x;
    int lane = tid & 31;

    for (int i = tid; i < NBKT; i += NTH) hist[i] = 0;
    unsigned char myl = g_lab[r];
    if (tid == 0) s_ncand = 0;
    __syncthreads();

    // ---- pass 1: load + histogram + same-label sum ----
    float ssum = 0.f;
    const float4* Srow = (const float4*)(g_S + (size_t)r * BN);
    for (int i4 = tid; i4 < BN / 4; i4 += NTH) {
        float4 v = Srow[i4];
        ((float4*)vals)[i4] = v;
        float vv[4] = {v.x, v.y, v.z, v.w};
        int j0 = i4 * 4;
        #pragma unroll
        for (int c = 0; c < 4; c++) {
            int j = j0 + c;
            if (j == r) continue;
            float x = vv[c];
            atomicAdd(&hist[bucket_of(x)], 1u);
            if (__ldg(&g_lab[j]) == myl) ssum += x;
        }
    }
    __syncthreads();

    // ---- warp 0: find bucket where descending cumulative count crosses TOPK ----
    if (tid < 32) {
        const int ch = NBKT / 32;                 // 32 buckets per lane
        int hi = NBKT - 1 - lane * ch;
        unsigned pc = 0;
        #pragma unroll
        for (int t = 0; t < ch; t++) pc += hist[hi - t];
        unsigned inc = pc;
        #pragma unroll
        for (int off = 1; off < 32; off <<= 1) {
            unsigned u = __shfl_up_sync(0xffffffffu, inc, off);
            if (lane >= off) inc += u;
        }
        unsigned exc = inc - pc;
        if (exc < TOPK && inc >= TOPK) {
            unsigned cum = exc;
            #pragma unroll
            for (int t = 0; t < ch; t++) {
                unsigned c = hist[hi - t];
                if (cum + c >= TOPK) { s_bsel = hi - t; s_above = (int)cum; break; }
                cum += c;
            }
        }
    }
    __syncthreads();
    int bsel = s_bsel;
    int need = TOPK - s_above;     // 1..TOPK, count to take from within bucket bsel

    // ---- pass 2: sum strictly-above-bucket + gather in-bucket candidates ----
    float tsum = 0.f;
    for (int i4 = tid; i4 < BN / 4; i4 += NTH) {
        float4 v = ((const float4*)vals)[i4];
        float vv[4] = {v.x, v.y, v.z, v.w};
        int j0 = i4 * 4;
        #pragma unroll
        for (int c = 0; c < 4; c++) {
            int j = j0 + c;
            if (j == r) continue;
            float x = vv[c];
            int b = bucket_of(x);
            if (b > bsel) tsum += x;
            else if (b == bsel) {
                int p = atomicAdd(&s_ncand, 1);
                if (p < CAND_MAX) cand[p] = x;
            }
        }
    }
    __syncthreads();
    int ncand = min(s_ncand, CAND_MAX);

    // ---- mini fkey-radix over candidates: exact key of need-th largest ----
    unsigned pref = 0, prefmask = 0;
    int rem = need;
    for (int shift = 24; shift >= 0; shift -= 8) {
        for (int i = tid; i < 256; i += NTH) hist[i] = 0;
        __syncthreads();
        for (int i = tid; i < ncand; i += NTH) {
            unsigned k = fkey(cand[i]);
            if ((k & prefmask) == pref) atomicAdd(&hist[(k >> shift) & 255u], 1u);
        }
        __syncthreads();
        if (tid < 32) {                           // warp suffix-select over 256 buckets
            const int ch = 256 / 32;
            int hi = 255 - lane * ch;
            unsigned pc = 0;
            #pragma unroll
            for (int t = 0; t < ch; t++) pc += hist[hi - t];
            unsigned inc = pc;
            #pragma unroll
            for (int off = 1; off < 32; off <<= 1) {
                unsigned u = __shfl_up_sync(0xffffffffu, inc, off);
                if (lane >= off) inc += u;
            }
            unsigned exc = inc - pc;
            if (exc < (unsigned)rem && inc >= (unsigned)rem) {
                unsigned cum = exc;
                #pragma unroll
                for (int t = 0; t < ch; t++) {
                    unsigned c = hist[hi - t];
                    if (cum + c >= (unsigned)rem) { s_sel2 = hi - t; s_above2 = (int)cum; break; }
                    cum += c;
                }
            }
        }
        __syncthreads();
        pref     |= ((unsigned)s_sel2) << shift;
        prefmask |= 0xFFu << shift;
        rem      -= s_above2;
        __syncthreads();
    }
    // pref = exact key of the need-th largest in-bucket value; rem = ties still to take

    // ---- pass 3: deterministic sum of strictly-above-threshold within bucket ----
    float gsum = 0.f;
    for (int i4 = tid; i4 < BN / 4; i4 += NTH) {
        float4 v = ((const float4*)vals)[i4];
        float vv[4] = {v.x, v.y, v.z, v.w};
        int j0 = i4 * 4;
        #pragma unroll
        for (int c = 0; c < 4; c++) {
            int j = j0 + c;
            if (j == r) continue;
            float x = vv[c];
            if (bucket_of(x) == bsel && fkey(x) > pref) gsum += x;
        }
    }

    // ---- block reduction (fixed tree: deterministic) ----
    float A = tsum + gsum, B = ssum;
    #pragma unroll
    for (int o = 16; o; o >>= 1) {
        A += __shfl_xor_sync(0xffffffffu, A, o);
        B += __shfl_xor_sync(0xffffffffu, B, o);
    }
    if (lane == 0) { wredA[tid >> 5] = A; wredB[tid >> 5] = B; }
    __syncthreads();
    if (tid == 0) {
        float At = 0.f, Bt = 0.f;
        #pragma unroll
        for (int w = 0; w < NTH / 32; w++) { At += wredA[w]; Bt += wredB[w]; }
        g_partial[r] = At + (float)rem * fval(pref) - Bt;
    }
}

// ============================ final scalar reduce ============================
__global__ void reduce_kernel(float* __restrict__ out) {
    __shared__ double red[256];
    int tid = threadIdx.x;
    double s = 0.0;
    for (int i = tid; i < BN; i += 256) s += (double)g_partial[i];
    red[tid] = s;
    __syncthreads();
    for (int st = 128; st > 0; st >>= 1) {
        if (tid < st) red[tid] += red[tid + st];
        __syncthreads();
    }
    if (tid == 0) out[0] = (float)(red[0] / (double)BN);
}

// ============================ launch ============================
extern "C" void kernel_launch(void* const* d_in, const int* in_sizes, int n_in,
                              void* d_out, int out_size) {
    (void)in_sizes; (void)n_in; (void)out_size;
    const float*        feats = (const float*)d_in[0];
    const unsigned int* labw  = (const unsigned int*)d_in[1];
    float*              out   = (float*)d_out;

    normalize_kernel<<<BN / 8, 256>>>(feats);
    label_kernel<<<1, 256>>>(labw);
    dim3 g(BN / GBLK, BN / GBLK);
    gemm_kernel<<<g, 256>>>();
    topk_kernel<<<BN, NTH>>>();
    reduce_kernel<<<1, 256>>>(out);
}

// round 4
// speedup vs baseline: 2.0973x; 1.3358x over previous
#include <cuda_runtime.h>
#include <cuda_bf16.h>
#include <cstdint>

#define BN   8192
#define DIM  128
#define TOPK 128

#define NTH  512          // topk threads
#define NBKT 1024

// -------- device scratch (no allocation allowed) --------
__device__ __nv_bfloat16 g_fnb[(size_t)BN * DIM];  // normalized feats, bf16
__device__ float         g_S[(size_t)BN * BN];     // Gram matrix (256 MB)
__device__ unsigned char g_lab[BN];
__device__ float         g_partial[BN];

// ============================ helpers ============================
__device__ __forceinline__ uint32_t smem_u32(const void* p) {
    uint32_t a;
    asm("{ .reg .u64 t; cvta.to.shared.u64 t, %1; cvt.u32.u64 %0, t; }" : "=r"(a) : "l"(p));
    return a;
}
__device__ __forceinline__ void ldmatrix_x4(uint32_t& r0, uint32_t& r1, uint32_t& r2, uint32_t& r3, uint32_t a) {
    asm volatile("ldmatrix.sync.aligned.m8n8.x4.shared.b16 {%0,%1,%2,%3}, [%4];"
                 : "=r"(r0), "=r"(r1), "=r"(r2), "=r"(r3) : "r"(a));
}
__device__ __forceinline__ void ldmatrix_x2(uint32_t& r0, uint32_t& r1, uint32_t a) {
    asm volatile("ldmatrix.sync.aligned.m8n8.x2.shared.b16 {%0,%1}, [%2];"
                 : "=r"(r0), "=r"(r1) : "r"(a));
}
__device__ __forceinline__ void mma_bf16(float* d, const uint32_t* a, const uint32_t* b) {
    asm volatile(
        "mma.sync.aligned.m16n8k16.row.col.f32.bf16.bf16.f32 "
        "{%0,%1,%2,%3}, {%4,%5,%6,%7}, {%8,%9}, {%0,%1,%2,%3};"
        : "+f"(d[0]), "+f"(d[1]), "+f"(d[2]), "+f"(d[3])
        : "r"(a[0]), "r"(a[1]), "r"(a[2]), "r"(a[3]), "r"(b[0]), "r"(b[1]));
}

// ---- monotone float<->uint key ----
__device__ __forceinline__ unsigned fkey(float x) {
    unsigned u = __float_as_uint(x);
    return (u & 0x80000000u) ? ~u : (u | 0x80000000u);
}
__device__ __forceinline__ float fval(unsigned k) {
    return __uint_as_float((k & 0x80000000u) ? (k ^ 0x80000000u) : ~k);
}
__device__ __forceinline__ int bucket_of(float v) {
    int b = (int)fmaf(v, 512.f, 512.f);
    return max(0, min(NBKT - 1, b));
}

// ============================ normalize -> bf16 ============================
__global__ void normalize_kernel(const float* __restrict__ feats) {
    int w    = (blockIdx.x * blockDim.x + threadIdx.x) >> 5;
    int lane = threadIdx.x & 31;
    if (w >= BN) return;
    float4 v = ((const float4*)(feats + (size_t)w * DIM))[lane];
    float ss = v.x * v.x + v.y * v.y + v.z * v.z + v.w * v.w;
    #pragma unroll
    for (int o = 16; o; o >>= 1) ss += __shfl_xor_sync(0xffffffffu, ss, o);
    float inv = rsqrtf(ss);
    __nv_bfloat162* dst = (__nv_bfloat162*)(g_fnb + (size_t)w * DIM);
    dst[lane * 2 + 0] = __floats2bfloat162_rn(v.x * inv, v.y * inv);
    dst[lane * 2 + 1] = __floats2bfloat162_rn(v.z * inv, v.w * inv);
}

// ============================ labels -> u8 (int64/int32 tolerant) ============================
__global__ void label_kernel(const unsigned int* __restrict__ words) {
    int tid = threadIdx.x;
    int any = 0;
    for (int i = tid; i < BN / 2; i += blockDim.x) any |= (words[2 * i + 1] != 0u);
    int tot  = __syncthreads_or(any);
    int is64 = (tot == 0);
    for (int i = tid; i < BN; i += blockDim.x)
        g_lab[i] = (unsigned char)(is64 ? words[2 * i] : words[i]);
}

// ============================ bf16 mma.sync Gram GEMM ============================
// CTA tile 128x128, K=128 fully smem-resident. 8 warps (2x4), warp tile 64x32.
// Smem rows padded to 136 bf16 (272B) => conflict-free ldmatrix.
#define ASTR 136
__global__ void __launch_bounds__(256) gemm_mma_kernel() {
    extern __shared__ __align__(16) char sm[];
    __nv_bfloat16* Asm = (__nv_bfloat16*)sm;                       // [128][136]
    __nv_bfloat16* Bsm = (__nv_bfloat16*)(sm + 128 * ASTR * 2);    // [128][136]

    int tid  = threadIdx.x;
    int wid  = tid >> 5, lane = tid & 31;
    int tm   = blockIdx.x, tn = blockIdx.y;
    int wm   = wid >> 2, wn = wid & 3;       // warp grid 2x4

    // ---- load A,B tiles (16B granules; 16 granules per 128-elem row) ----
    const uint4* F = (const uint4*)g_fnb;
    #pragma unroll
    for (int it = 0; it < 8; it++) {
        int i = tid + it * 256;              // 2048 granules
        int r = i >> 4, g = i & 15;
        uint4 va = F[(size_t)(tm * 128 + r) * 16 + g];
        uint4 vb = F[(size_t)(tn * 128 + r) * 16 + g];
        *(uint4*)(Asm + r * ASTR + g * 8) = va;
        *(uint4*)(Bsm + r * ASTR + g * 8) = vb;
    }
    __syncthreads();

    // ---- mma mainloop ----
    float acc[4][4][4];
    #pragma unroll
    for (int i = 0; i < 4; i++)
        #pragma unroll
        for (int j = 0; j < 4; j++)
            #pragma unroll
            for (int c = 0; c < 4; c++) acc[i][j][c] = 0.f;

    // per-lane ldmatrix base addresses (element offsets; k varies in loop)
    // A x4: lane -> row (m0 + lane%16), col half (lane>>4)*8
    // B x2: lanes 0-15 -> row (n0 + lane%8), col half ((lane>>3)&1)*8
    uint32_t a_base = smem_u32(Asm) + ((wm * 64 + (lane & 15)) * ASTR + (lane >> 4) * 8) * 2;
    uint32_t b_base = smem_u32(Bsm) + ((wn * 32 + (lane & 7)) * ASTR + ((lane >> 3) & 1) * 8) * 2;

    #pragma unroll
    for (int k0 = 0; k0 < DIM; k0 += 16) {
        uint32_t af[4][4], bf[4][2];
        #pragma unroll
        for (int mt = 0; mt < 4; mt++)
            ldmatrix_x4(af[mt][0], af[mt][1], af[mt][2], af[mt][3],
                        a_base + (mt * 16 * ASTR + k0) * 2);
        #pragma unroll
        for (int nt = 0; nt < 4; nt++)
            ldmatrix_x2(bf[nt][0], bf[nt][1],
                        b_base + (nt * 8 * ASTR + k0) * 2);
        #pragma unroll
        for (int mt = 0; mt < 4; mt++)
            #pragma unroll
            for (int nt = 0; nt < 4; nt++)
                mma_bf16(acc[mt][nt], af[mt], bf[nt]);
    }
    __syncthreads();

    // ---- epilogue: stage fp32 tile in smem, then coalesced float4 stores ----
    float* stage = (float*)sm;               // [128][132] = 67584B <= 69632B
    const int SST = 132;
    #pragma unroll
    for (int mt = 0; mt < 4; mt++) {
        int r0 = wm * 64 + mt * 16 + (lane >> 2);
        #pragma unroll
        for (int nt = 0; nt < 4; nt++) {
            int c0 = wn * 32 + nt * 8 + (lane & 3) * 2;
            *(float2*)&stage[r0 * SST + c0]       = make_float2(acc[mt][nt][0], acc[mt][nt][1]);
            *(float2*)&stage[(r0 + 8) * SST + c0] = make_float2(acc[mt][nt][2], acc[mt][nt][3]);
        }
    }
    __syncthreads();
    #pragma unroll
    for (int it = 0; it < 16; it++) {
        int i = tid + it * 256;              // 4096 float4s
        int row = i >> 5, c4 = i & 31;
        float4 v = ((float4*)&stage[row * SST])[c4];
        ((float4*)(g_S + (size_t)(tm * 128 + row) * BN + tn * 128))[c4] = v;
    }
}

// ============================ poison diagonal ============================
__global__ void diag_kernel() {
    int i = blockIdx.x * blockDim.x + threadIdx.x;
    if (i < BN) g_S[(size_t)i * BN + i] = -1e9f;
}

// ============================ per-row top-K sum + same-label sum ============================
__global__ void __launch_bounds__(NTH) topk_kernel() {
    __shared__ float         vals[BN];     // 32 KB
    __shared__ unsigned      hist[NBKT];   // 4 KB (low 256 reused by mini-radix)
    __shared__ unsigned char lab[BN];      // 8 KB
    __shared__ float         wredA[NTH / 32], wredB[NTH / 32];
    __shared__ int           s_bsel, s_above, s_sel2, s_above2;

    int r    = blockIdx.x;
    int tid  = threadIdx.x;
    int lane = tid & 31;

    for (int i = tid; i < NBKT; i += NTH) hist[i] = 0;
    for (int i = tid * 4; i < BN; i += NTH * 4) *(uchar4*)&lab[i] = *(const uchar4*)&g_lab[i];
    unsigned char myl = g_lab[r];
    __syncthreads();
    if (tid == 0) lab[r] = 0xFF;           // sentinel: excludes self from label sum
    __syncthreads();

    // ---- pass 1: load + histogram + same-label sum (diag pre-poisoned to -1e9) ----
    float ssum = 0.f;
    const float4* Srow = (const float4*)(g_S + (size_t)r * BN);
    for (int i4 = tid; i4 < BN / 4; i4 += NTH) {
        float4 v = Srow[i4];
        ((float4*)vals)[i4] = v;
        float vv[4] = {v.x, v.y, v.z, v.w};
        int j0 = i4 * 4;
        #pragma unroll
        for (int c = 0; c < 4; c++) {
            float x = vv[c];
            atomicAdd(&hist[bucket_of(x)], 1u);
            if (lab[j0 + c] == myl) ssum += x;
        }
    }
    __syncthreads();

    // ---- warp 0: bucket containing K-th largest ----
    if (tid < 32) {
        const int ch = NBKT / 32;
        int hi = NBKT - 1 - lane * ch;
        unsigned pc = 0;
        #pragma unroll
        for (int t = 0; t < ch; t++) pc += hist[hi - t];
        unsigned inc = pc;
        #pragma unroll
        for (int off = 1; off < 32; off <<= 1) {
            unsigned u = __shfl_up_sync(0xffffffffu, inc, off);
            if (lane >= off) inc += u;
        }
        unsigned exc = inc - pc;
        if (exc < TOPK && inc >= TOPK) {
            unsigned cum = exc;
            #pragma unroll
            for (int t = 0; t < ch; t++) {
                unsigned c = hist[hi - t];
                if (cum + c >= TOPK) { s_bsel = hi - t; s_above = (int)cum; break; }
                cum += c;
            }
        }
    }
    __syncthreads();
    int bsel = s_bsel;
    int rem  = TOPK - s_above;

    // ---- pass 2: sum above-bucket + per-thread candidate list (<=16, exact bound) ----
    float tsum = 0.f;
    float lc[16];
    int   nlc = 0;
    for (int i4 = tid; i4 < BN / 4; i4 += NTH) {
        float4 v = ((const float4*)vals)[i4];
        float vv[4] = {v.x, v.y, v.z, v.w};
        #pragma unroll
        for (int c = 0; c < 4; c++) {
            float x = vv[c];
            int b = bucket_of(x);
            if (b > bsel) tsum += x;
            else if (b == bsel) lc[nlc++] = x;
        }
    }
    __syncthreads();

    // ---- mini fkey-radix over candidates -> exact key of rem-th largest ----
    unsigned pref = 0, prefmask = 0;
    for (int shift = 24; shift >= 0; shift -= 8) {
        for (int i = tid; i < 256; i += NTH) hist[i] = 0;
        __syncthreads();
        for (int t = 0; t < nlc; t++) {
            unsigned k = fkey(lc[t]);
            if ((k & prefmask) == pref) atomicAdd(&hist[(k >> shift) & 255u], 1u);
        }
        __syncthreads();
        if (tid < 32) {
            const int ch = 256 / 32;
            int hi = 255 - lane * ch;
            unsigned pc = 0;
            #pragma unroll
            for (int t = 0; t < ch; t++) pc += hist[hi - t];
            unsigned inc = pc;
            #pragma unroll
            for (int off = 1; off < 32; off <<= 1) {
                unsigned u = __shfl_up_sync(0xffffffffu, inc, off);
                if (lane >= off) inc += u;
            }
            unsigned exc = inc - pc;
            if (exc < (unsigned)rem && inc >= (unsigned)rem) {
                unsigned cum = exc;
                #pragma unroll
                for (int t = 0; t < ch; t++) {
                    unsigned c = hist[hi - t];
                    if (cum + c >= (unsigned)rem) { s_sel2 = hi - t; s_above2 = (int)cum; break; }
                    cum += c;
                }
            }
        }
        __syncthreads();
        pref     |= ((unsigned)s_sel2) << shift;
        prefmask |= 0xFFu << shift;
        rem      -= s_above2;
        __syncthreads();
    }

    // ---- above-threshold in-bucket sum from local lists (deterministic) ----
    float gsum = 0.f;
    for (int t = 0; t < nlc; t++)
        if (fkey(lc[t]) > pref) gsum += lc[t];

    // ---- fixed-tree block reduction ----
    float A = tsum + gsum, B = ssum;
    #pragma unroll
    for (int o = 16; o; o >>= 1) {
        A += __shfl_xor_sync(0xffffffffu, A, o);
        B += __shfl_xor_sync(0xffffffffu, B, o);
    }
    if (lane == 0) { wredA[tid >> 5] = A; wredB[tid >> 5] = B; }
    __syncthreads();
    if (tid == 0) {
        float At = 0.f, Bt = 0.f;
        #pragma unroll
        for (int w = 0; w < NTH / 32; w++) { At += wredA[w]; Bt += wredB[w]; }
        g_partial[r] = At + (float)rem * fval(pref) - Bt;
    }
}

// ============================ final scalar reduce ============================
__global__ void reduce_kernel(float* __restrict__ out) {
    __shared__ double red[256];
    int tid = threadIdx.x;
    double s = 0.0;
    for (int i = tid; i < BN; i += 256) s += (double)g_partial[i];
    red[tid] = s;
    __syncthreads();
    for (int st = 128; st > 0; st >>= 1) {
        if (tid < st) red[tid] += red[tid + st];
        __syncthreads();
    }
    if (tid == 0) out[0] = (float)(red[0] / (double)BN);
}

// ============================ launch ============================
extern "C" void kernel_launch(void* const* d_in, const int* in_sizes, int n_in,
                              void* d_out, int out_size) {
    (void)in_sizes; (void)n_in; (void)out_size;
    const float*        feats = (const float*)d_in[0];
    const unsigned int* labw  = (const unsigned int*)d_in[1];
    float*              out   = (float*)d_out;

    const int smem = 2 * 128 * ASTR * 2;   // 69632 B
    cudaFuncSetAttribute(gemm_mma_kernel, cudaFuncAttributeMaxDynamicSharedMemorySize, smem);

    normalize_kernel<<<BN / 8, 256>>>(feats);
    label_kernel<<<1, 256>>>(labw);
    dim3 g(BN / 128, BN / 128);
    gemm_mma_kernel<<<g, 256, smem>>>();
    diag_kernel<<<BN / 256, 256>>>();
    topk_kernel<<<BN, NTH>>>();
    reduce_kernel<<<1, 256>>>(out);
}

// round 6
// speedup vs baseline: 2.1552x; 1.0276x over previous
#include <cuda_runtime.h>
#include <cuda_bf16.h>
#include <cstdint>

#define BN   8192
#define DIM  128
#define TOPK 128
#define NTH  512
#define NBKT 2048
#define ASTR 136

// -------- device scratch --------
__device__ __nv_bfloat16 g_fnb[(size_t)BN * DIM];  // normalized feats, bf16
__device__ __nv_bfloat16 g_Sb[(size_t)BN * BN];    // Gram matrix, bf16 (128 MB)
__device__ unsigned char g_lab[BN];
__device__ float         g_partial[BN];

// ============================ helpers ============================
__device__ __forceinline__ uint32_t smem_u32(const void* p) {
    uint32_t a;
    asm("{ .reg .u64 t; cvta.to.shared.u64 t, %1; cvt.u32.u64 %0, t; }" : "=r"(a) : "l"(p));
    return a;
}
__device__ __forceinline__ unsigned pack_bf16x2(float lo, float hi) {
    unsigned r;
    asm("cvt.rn.bf16x2.f32 %0, %1, %2;" : "=r"(r) : "f"(hi), "f"(lo));
    return r;
}
__device__ __forceinline__ void ldmatrix_x4(uint32_t& r0, uint32_t& r1, uint32_t& r2, uint32_t& r3, uint32_t a) {
    asm volatile("ldmatrix.sync.aligned.m8n8.x4.shared.b16 {%0,%1,%2,%3}, [%4];"
                 : "=r"(r0), "=r"(r1), "=r"(r2), "=r"(r3) : "r"(a));
}
__device__ __forceinline__ void ldmatrix_x2(uint32_t& r0, uint32_t& r1, uint32_t a) {
    asm volatile("ldmatrix.sync.aligned.m8n8.x2.shared.b16 {%0,%1}, [%2];"
                 : "=r"(r0), "=r"(r1) : "r"(a));
}
__device__ __forceinline__ void mma_bf16(float* d, const uint32_t* a, const uint32_t* b) {
    asm volatile(
        "mma.sync.aligned.m16n8k16.row.col.f32.bf16.bf16.f32 "
        "{%0,%1,%2,%3}, {%4,%5,%6,%7}, {%8,%9}, {%0,%1,%2,%3};"
        : "+f"(d[0]), "+f"(d[1]), "+f"(d[2]), "+f"(d[3])
        : "r"(a[0]), "r"(a[1]), "r"(a[2]), "r"(a[3]), "r"(b[0]), "r"(b[1]));
}

// 16-bit monotone key for bf16 bit patterns
__device__ __forceinline__ unsigned fkey16(unsigned x) {
    return (x ^ (0x8000u | (0x7FFFu & (0u - (x >> 15))))) & 0xFFFFu;
}
__device__ __forceinline__ float val16(unsigned k) {   // key -> float value
    unsigned b = (k & 0x8000u) ? (k ^ 0x8000u) : ((~k) & 0xFFFFu);
    return __uint_as_float(b << 16);
}

// warp-collective: find bucket (descending) where cumulative count crosses target
__device__ __forceinline__ void warp_suffix_select(const unsigned* h, int nb, int target,
                                                   int* out_sel, int* out_above, int lane) {
    int ch = nb >> 5;
    int hi = nb - 1 - lane * ch;
    unsigned pc = 0;
    for (int t = 0; t < ch; t++) pc += h[hi - t];
    unsigned inc = pc;
    #pragma unroll
    for (int off = 1; off < 32; off <<= 1) {
        unsigned u = __shfl_up_sync(0xffffffffu, inc, off);
        if (lane >= off) inc += u;
    }
    unsigned exc = inc - pc;
    if (exc < (unsigned)target && inc >= (unsigned)target) {
        unsigned cum = exc;
        for (int t = 0; t < ch; t++) {
            unsigned c = h[hi - t];
            if (cum + c >= (unsigned)target) { *out_sel = hi - t; *out_above = (int)cum; break; }
            cum += c;
        }
    }
}

// ============================ normalize -> bf16 ============================
__global__ void normalize_kernel(const float* __restrict__ feats) {
    int w    = (blockIdx.x * blockDim.x + threadIdx.x) >> 5;
    int lane = threadIdx.x & 31;
    if (w >= BN) return;
    float4 v = ((const float4*)(feats + (size_t)w * DIM))[lane];
    float ss = v.x * v.x + v.y * v.y + v.z * v.z + v.w * v.w;
    #pragma unroll
    for (int o = 16; o; o >>= 1) ss += __shfl_xor_sync(0xffffffffu, ss, o);
    float inv = rsqrtf(ss);
    unsigned* dst = (unsigned*)(g_fnb + (size_t)w * DIM);
    dst[lane * 2 + 0] = pack_bf16x2(v.x * inv, v.y * inv);
    dst[lane * 2 + 1] = pack_bf16x2(v.z * inv, v.w * inv);
}

// ============================ labels -> u8 (int64/int32 tolerant) ============================
__global__ void label_kernel(const unsigned int* __restrict__ words) {
    int tid = threadIdx.x;
    int any = 0;
    for (int i = tid; i < BN / 2; i += blockDim.x) any |= (words[2 * i + 1] != 0u);
    int tot  = __syncthreads_or(any);
    int is64 = (tot == 0);
    for (int i = tid; i < BN; i += blockDim.x)
        g_lab[i] = (unsigned char)(is64 ? words[2 * i] : words[i]);
}

// ============================ bf16 mma.sync symmetric Gram GEMM ============================
// Upper-triangle tiles only (tn>=tm). Direct tile + mirrored (transposed) tile, bf16 out.
__global__ void __launch_bounds__(256, 2) gemm_mma_kernel() {
    int tm = blockIdx.x, tn = blockIdx.y;
    if (tn < tm) return;

    extern __shared__ __align__(16) char sm[];
    __nv_bfloat16* Asm = (__nv_bfloat16*)sm;                                       // [128][136]
    __nv_bfloat16* Bsm = (tm == tn) ? Asm : (__nv_bfloat16*)(sm + 128 * ASTR * 2); // [128][136]

    int tid  = threadIdx.x;
    int wid  = tid >> 5, lane = tid & 31;
    int wm   = wid >> 2, wn = wid & 3;       // warp grid 2x4

    const uint4* F = (const uint4*)g_fnb;
    #pragma unroll
    for (int it = 0; it < 8; it++) {
        int i = tid + it * 256;
        int r = i >> 4, g = i & 15;
        *(uint4*)(Asm + r * ASTR + g * 8) = F[(size_t)(tm * 128 + r) * 16 + g];
    }
    if (tm != tn) {
        #pragma unroll
        for (int it = 0; it < 8; it++) {
            int i = tid + it * 256;
            int r = i >> 4, g = i & 15;
            *(uint4*)(Bsm + r * ASTR + g * 8) = F[(size_t)(tn * 128 + r) * 16 + g];
        }
    }
    __syncthreads();

    float acc[4][4][4];
    #pragma unroll
    for (int i = 0; i < 4; i++)
        #pragma unroll
        for (int j = 0; j < 4; j++)
            #pragma unroll
            for (int c = 0; c < 4; c++) acc[i][j][c] = 0.f;

    uint32_t a_base = smem_u32(Asm) + ((wm * 64 + (lane & 15)) * ASTR + (lane >> 4) * 8) * 2;
    uint32_t b_base = smem_u32(Bsm) + ((wn * 32 + (lane & 7)) * ASTR + ((lane >> 3) & 1) * 8) * 2;

    #pragma unroll
    for (int k0 = 0; k0 < DIM; k0 += 16) {
        uint32_t af[4][4], bf[4][2];
        #pragma unroll
        for (int mt = 0; mt < 4; mt++)
            ldmatrix_x4(af[mt][0], af[mt][1], af[mt][2], af[mt][3],
                        a_base + (mt * 16 * ASTR + k0) * 2);
        #pragma unroll
        for (int nt = 0; nt < 4; nt++)
            ldmatrix_x2(bf[nt][0], bf[nt][1],
                        b_base + (nt * 8 * ASTR + k0) * 2);
        #pragma unroll
        for (int mt = 0; mt < 4; mt++)
            #pragma unroll
            for (int nt = 0; nt < 4; nt++)
                mma_bf16(acc[mt][nt], af[mt], bf[nt]);
    }
    __syncthreads();

    // ---- epilogue: bf16 stage (direct) + XOR-swizzled transposed stage (mirror) ----
    __nv_bfloat16*  stage = (__nv_bfloat16*)sm;                 // [128][136]  34816 B
    unsigned short* st2   = (unsigned short*)(sm + 34816);      // [128][128] swizzled 32768 B
    bool mir = (tm != tn);

    #pragma unroll
    for (int mt = 0; mt < 4; mt++) {
        int r0 = wm * 64 + mt * 16 + (lane >> 2);
        #pragma unroll
        for (int nt = 0; nt < 4; nt++) {
            int c0 = wn * 32 + nt * 8 + (lane & 3) * 2;
            unsigned p0 = pack_bf16x2(acc[mt][nt][0], acc[mt][nt][1]);
            unsigned p1 = pack_bf16x2(acc[mt][nt][2], acc[mt][nt][3]);
            *(unsigned*)&stage[r0 * ASTR + c0]       = p0;
            *(unsigned*)&stage[(r0 + 8) * ASTR + c0] = p1;
            if (mir) {
                int ra = r0, rb = r0 + 8;
                st2[(c0)     * 128 + (((ra >> 3) ^ (c0 & 15)) * 8)       + (ra & 7)] = (unsigned short)(p0 & 0xFFFF);
                st2[(c0 + 1) * 128 + (((ra >> 3) ^ ((c0 + 1) & 15)) * 8) + (ra & 7)] = (unsigned short)(p0 >> 16);
                st2[(c0)     * 128 + (((rb >> 3) ^ (c0 & 15)) * 8)       + (rb & 7)] = (unsigned short)(p1 & 0xFFFF);
                st2[(c0 + 1) * 128 + (((rb >> 3) ^ ((c0 + 1) & 15)) * 8) + (rb & 7)] = (unsigned short)(p1 >> 16);
            }
        }
    }
    __syncthreads();
    if (!mir && tid < 128) stage[tid * ASTR + tid] = __float2bfloat16(-1e9f);  // diag poison
    __syncthreads();

    // direct tile store (coalesced uint4)
    #pragma unroll
    for (int it = 0; it < 8; it++) {
        int i = tid + it * 256;            // 2048 granules
        int row = i >> 4, g = i & 15;
        uint4 v = *(uint4*)&stage[row * ASTR + g * 8];
        ((uint4*)(g_Sb + (size_t)(tm * 128 + row) * BN + tn * 128))[g] = v;
    }
    // mirror tile store (reads swizzled st2, conflict-free; coalesced out)
    if (mir) {
        #pragma unroll
        for (int it = 0; it < 8; it++) {
            int i = tid + it * 256;
            int crow = i >> 4, g = i & 15;
            int pg = g ^ (crow & 15);
            uint4 v = *(uint4*)&st2[crow * 128 + pg * 8];
            ((uint4*)(g_Sb + (size_t)(tn * 128 + crow) * BN + tm * 128))[g] = v;
        }
    }
}

// ============================ per-row top-K sum + same-label sum (bf16 keys) ============================
__global__ void __launch_bounds__(NTH) topk_kernel() {
    __shared__ unsigned      sval[BN / 2];   // 16 KB bf16 pairs
    __shared__ unsigned      hist[NBKT];     // 8 KB (low 256 reused by mini-radix)
    __shared__ unsigned char lab[BN];        // 8 KB
    __shared__ float         wredA[NTH / 32], wredB[NTH / 32];
    __shared__ int           s_bsel, s_above, s_sel2, s_above2;

    int r    = blockIdx.x;
    int tid  = threadIdx.x;
    int lane = tid & 31;

    for (int i = tid; i < NBKT; i += NTH) hist[i] = 0;
    for (int i = tid * 4; i < BN; i += NTH * 4) *(uchar4*)&lab[i] = *(const uchar4*)&g_lab[i];
    unsigned char myl = g_lab[r];
    __syncthreads();
    if (tid == 0) lab[r] = 0xFF;   // sentinel (labels < 200)
    __syncthreads();

    unsigned mylw = (unsigned)myl * 0x01010101u;
    float ssum = 0.f;

    // ---- pass 1: load + histogram + same-label sum ----
    const uint4* S4 = (const uint4*)(g_Sb + (size_t)r * BN);
    #pragma unroll
    for (int it = 0; it < 2; it++) {
        int i4 = tid + it * NTH;             // 0..1023, 8 elems each
        uint4 v = S4[i4];
        ((uint4*)sval)[i4] = v;
        int j0 = i4 * 8;
        unsigned e0 = __vcmpeq4(*(const unsigned*)&lab[j0],     mylw);
        unsigned e1 = __vcmpeq4(*(const unsigned*)&lab[j0 + 4], mylw);
        unsigned w;
        w = v.x;
        atomicAdd(&hist[fkey16(w & 0xFFFFu) >> 5], 1u);
        atomicAdd(&hist[fkey16(w >> 16)     >> 5], 1u);
        if (e0 & 0x000000FFu) ssum += __uint_as_float(w << 16);
        if (e0 & 0x0000FF00u) ssum += __uint_as_float(w & 0xFFFF0000u);
        w = v.y;
        atomicAdd(&hist[fkey16(w & 0xFFFFu) >> 5], 1u);
        atomicAdd(&hist[fkey16(w >> 16)     >> 5], 1u);
        if (e0 & 0x00FF0000u) ssum += __uint_as_float(w << 16);
        if (e0 & 0xFF000000u) ssum += __uint_as_float(w & 0xFFFF0000u);
        w = v.z;
        atomicAdd(&hist[fkey16(w & 0xFFFFu) >> 5], 1u);
        atomicAdd(&hist[fkey16(w >> 16)     >> 5], 1u);
        if (e1 & 0x000000FFu) ssum += __uint_as_float(w << 16);
        if (e1 & 0x0000FF00u) ssum += __uint_as_float(w & 0xFFFF0000u);
        w = v.w;
        atomicAdd(&hist[fkey16(w & 0xFFFFu) >> 5], 1u);
        atomicAdd(&hist[fkey16(w >> 16)     >> 5], 1u);
        if (e1 & 0x00FF0000u) ssum += __uint_as_float(w << 16);
        if (e1 & 0xFF000000u) ssum += __uint_as_float(w & 0xFFFF0000u);
    }
    __syncthreads();

    if (tid < 32) warp_suffix_select(hist, NBKT, TOPK, &s_bsel, &s_above, lane);
    __syncthreads();
    int bsel = s_bsel;
    int rem  = TOPK - s_above;

    // ---- pass 2: sum above-bucket + per-thread key candidates (<=16, exact bound) ----
    float tsum = 0.f;
    unsigned short lck[16];
    int nlc = 0;
    #pragma unroll
    for (int it = 0; it < 8; it++) {
        int i = tid + it * NTH;              // 0..4095 u32
        unsigned w = sval[i];
        unsigned klo = fkey16(w & 0xFFFFu), khi = fkey16(w >> 16);
        int blo = (int)(klo >> 5), bhi = (int)(khi >> 5);
        if (blo > bsel) tsum += __uint_as_float(w << 16);
        else if (blo == bsel) lck[nlc++] = (unsigned short)klo;
        if (bhi > bsel) tsum += __uint_as_float(w & 0xFFFF0000u);
        else if (bhi == bsel) lck[nlc++] = (unsigned short)khi;
    }
    __syncthreads();

    // ---- 2-pass mini-radix over 16-bit keys -> exact rem-th largest key ----
    unsigned pref = 0, pmask = 0;
    for (int shift = 8; shift >= 0; shift -= 8) {
        for (int i = tid; i < 256; i += NTH) hist[i] = 0;
        __syncthreads();
        for (int t = 0; t < nlc; t++) {
            unsigned k = lck[t];
            if ((k & pmask) == pref) atomicAdd(&hist[(k >> shift) & 255u], 1u);
        }
        __syncthreads();
        if (tid < 32) warp_suffix_select(hist, 256, rem, &s_sel2, &s_above2, lane);
        __syncthreads();
        pref  |= ((unsigned)s_sel2) << shift;
        pmask |= 0xFFu << shift;
        rem   -= s_above2;
        __syncthreads();
    }

    // ---- strictly-above-threshold in-bucket sum (deterministic per-thread order) ----
    float gsum = 0.f;
    for (int t = 0; t < nlc; t++)
        if ((unsigned)lck[t] > pref) gsum += val16(lck[t]);

    // ---- fixed-tree reduction ----
    float A = tsum + gsum, B = ssum;
    #pragma unroll
    for (int o = 16; o; o >>= 1) {
        A += __shfl_xor_sync(0xffffffffu, A, o);
        B += __shfl_xor_sync(0xffffffffu, B, o);
    }
    if (lane == 0) { wredA[tid >> 5] = A; wredB[tid >> 5] = B; }
    __syncthreads();
    if (tid == 0) {
        float At = 0.f, Bt = 0.f;
        #pragma unroll
        for (int w = 0; w < NTH / 32; w++) { At += wredA[w]; Bt += wredB[w]; }
        g_partial[r] = At + (float)rem * val16(pref) - Bt;
    }
}

// ============================ final scalar reduce ============================
__global__ void reduce_kernel(float* __restrict__ out) {
    __shared__ double red[256];
    int tid = threadIdx.x;
    double s = 0.0;
    for (int i = tid; i < BN; i += 256) s += (double)g_partial[i];
    red[tid] = s;
    __syncthreads();
    for (int st = 128; st > 0; st >>= 1) {
        if (tid < st) red[tid] += red[tid + st];
        __syncthreads();
    }
    if (tid == 0) out[0] = (float)(red[0] / (double)BN);
}

// ============================ launch ============================
extern "C" void kernel_launch(void* const* d_in, const int* in_sizes, int n_in,
                              void* d_out, int out_size) {
    (void)in_sizes; (void)n_in; (void)out_size;
    const float*        feats = (const float*)d_in[0];
    const unsigned int* labw  = (const unsigned int*)d_in[1];
    float*              out   = (float*)d_out;

    const int smem = 2 * 128 * ASTR * 2;   // 69632 B
    cudaFuncSetAttribute(gemm_mma_kernel, cudaFuncAttributeMaxDynamicSharedMemorySize, smem);

    normalize_kernel<<<BN / 8, 256>>>(feats);
    label_kernel<<<1, 256>>>(labw);
    dim3 g(BN / 128, BN / 128);
    gemm_mma_kernel<<<g, 256, smem>>>();
    topk_kernel<<<BN, NTH>>>();
    reduce_kernel<<<1, 256>>>(out);
}

// round 7
// speedup vs baseline: 3.3879x; 1.5719x over previous
#include <cuda_runtime.h>
#include <cuda_bf16.h>
#include <cstdint>

#define BN    8192
#define DIM   128
#define TOPK  128
#define NTH   512
#define NWARP (NTH / 32)
#define WSLOT 48
#define NBKT  1024
#define ASTR  136

// -------- device scratch --------
__device__ __nv_bfloat16 g_fnb[(size_t)BN * DIM];
__device__ __nv_bfloat16 g_Sb[(size_t)BN * BN];    // bf16 Gram (128 MB)
__device__ unsigned char g_lab[BN];
__device__ float         g_partial[BN];

// ============================ helpers ============================
__device__ __forceinline__ uint32_t smem_u32(const void* p) {
    uint32_t a;
    asm("{ .reg .u64 t; cvta.to.shared.u64 t, %1; cvt.u32.u64 %0, t; }" : "=r"(a) : "l"(p));
    return a;
}
__device__ __forceinline__ unsigned pack_bf16x2(float lo, float hi) {
    unsigned r;
    asm("cvt.rn.bf16x2.f32 %0, %1, %2;" : "=r"(r) : "f"(hi), "f"(lo));
    return r;
}
__device__ __forceinline__ void ldmatrix_x4(uint32_t& r0, uint32_t& r1, uint32_t& r2, uint32_t& r3, uint32_t a) {
    asm volatile("ldmatrix.sync.aligned.m8n8.x4.shared.b16 {%0,%1,%2,%3}, [%4];"
                 : "=r"(r0), "=r"(r1), "=r"(r2), "=r"(r3) : "r"(a));
}
__device__ __forceinline__ void ldmatrix_x2(uint32_t& r0, uint32_t& r1, uint32_t a) {
    asm volatile("ldmatrix.sync.aligned.m8n8.x2.shared.b16 {%0,%1}, [%2];"
                 : "=r"(r0), "=r"(r1) : "r"(a));
}
__device__ __forceinline__ void mma_bf16(float* d, const uint32_t* a, const uint32_t* b) {
    asm volatile(
        "mma.sync.aligned.m16n8k16.row.col.f32.bf16.bf16.f32 "
        "{%0,%1,%2,%3}, {%4,%5,%6,%7}, {%8,%9}, {%0,%1,%2,%3};"
        : "+f"(d[0]), "+f"(d[1]), "+f"(d[2]), "+f"(d[3])
        : "r"(a[0]), "r"(a[1]), "r"(a[2]), "r"(a[3]), "r"(b[0]), "r"(b[1]));
}

// 16-bit monotone key for bf16 bit patterns
__device__ __forceinline__ unsigned fkey16(unsigned x) {
    return (x ^ (0x8000u | (0x7FFFu & (0u - (x >> 15))))) & 0xFFFFu;
}
__device__ __forceinline__ float val16(unsigned k) {
    unsigned b = (k & 0x8000u) ? (k ^ 0x8000u) : ((~k) & 0xFFFFu);
    return __uint_as_float(b << 16);
}
// linear value bucket over [-1,1]
__device__ __forceinline__ int bucket_of(float v) {
    int b = (int)fmaf(v, 512.f, 512.f);
    return max(0, min(NBKT - 1, b));
}

__device__ __forceinline__ void warp_suffix_select(const unsigned* h, int nb, int target,
                                                   int* out_sel, int* out_above, int lane) {
    int ch = nb >> 5;
    int hi = nb - 1 - lane * ch;
    unsigned pc = 0;
    for (int t = 0; t < ch; t++) pc += h[hi - t];
    unsigned inc = pc;
    #pragma unroll
    for (int off = 1; off < 32; off <<= 1) {
        unsigned u = __shfl_up_sync(0xffffffffu, inc, off);
        if (lane >= off) inc += u;
    }
    unsigned exc = inc - pc;
    if (exc < (unsigned)target && inc >= (unsigned)target) {
        unsigned cum = exc;
        for (int t = 0; t < ch; t++) {
            unsigned c = h[hi - t];
            if (cum + c >= (unsigned)target) { *out_sel = hi - t; *out_above = (int)cum; break; }
            cum += c;
        }
    }
}

// ============================ normalize -> bf16 ============================
__global__ void normalize_kernel(const float* __restrict__ feats) {
    int w    = (blockIdx.x * blockDim.x + threadIdx.x) >> 5;
    int lane = threadIdx.x & 31;
    if (w >= BN) return;
    float4 v = ((const float4*)(feats + (size_t)w * DIM))[lane];
    float ss = v.x * v.x + v.y * v.y + v.z * v.z + v.w * v.w;
    #pragma unroll
    for (int o = 16; o; o >>= 1) ss += __shfl_xor_sync(0xffffffffu, ss, o);
    float inv = rsqrtf(ss);
    unsigned* dst = (unsigned*)(g_fnb + (size_t)w * DIM);
    dst[lane * 2 + 0] = pack_bf16x2(v.x * inv, v.y * inv);
    dst[lane * 2 + 1] = pack_bf16x2(v.z * inv, v.w * inv);
}

// ============================ labels -> u8 ============================
__global__ void label_kernel(const unsigned int* __restrict__ words) {
    int tid = threadIdx.x;
    int any = 0;
    for (int i = tid; i < BN / 2; i += blockDim.x) any |= (words[2 * i + 1] != 0u);
    int tot  = __syncthreads_or(any);
    int is64 = (tot == 0);
    for (int i = tid; i < BN; i += blockDim.x)
        g_lab[i] = (unsigned char)(is64 ? words[2 * i] : words[i]);
}

// ============================ bf16 mma.sync symmetric Gram GEMM ============================
__global__ void __launch_bounds__(256, 2) gemm_mma_kernel() {
    int tm = blockIdx.x, tn = blockIdx.y;
    if (tn < tm) return;

    extern __shared__ __align__(16) char sm[];
    __nv_bfloat16* Asm = (__nv_bfloat16*)sm;
    __nv_bfloat16* Bsm = (tm == tn) ? Asm : (__nv_bfloat16*)(sm + 128 * ASTR * 2);

    int tid  = threadIdx.x;
    int wid  = tid >> 5, lane = tid & 31;
    int wm   = wid >> 2, wn = wid & 3;

    const uint4* F = (const uint4*)g_fnb;
    #pragma unroll
    for (int it = 0; it < 8; it++) {
        int i = tid + it * 256;
        int r = i >> 4, g = i & 15;
        *(uint4*)(Asm + r * ASTR + g * 8) = F[(size_t)(tm * 128 + r) * 16 + g];
    }
    if (tm != tn) {
        #pragma unroll
        for (int it = 0; it < 8; it++) {
            int i = tid + it * 256;
            int r = i >> 4, g = i & 15;
            *(uint4*)(Bsm + r * ASTR + g * 8) = F[(size_t)(tn * 128 + r) * 16 + g];
        }
    }
    __syncthreads();

    float acc[4][4][4];
    #pragma unroll
    for (int i = 0; i < 4; i++)
        #pragma unroll
        for (int j = 0; j < 4; j++)
            #pragma unroll
            for (int c = 0; c < 4; c++) acc[i][j][c] = 0.f;

    uint32_t a_base = smem_u32(Asm) + ((wm * 64 + (lane & 15)) * ASTR + (lane >> 4) * 8) * 2;
    uint32_t b_base = smem_u32(Bsm) + ((wn * 32 + (lane & 7)) * ASTR + ((lane >> 3) & 1) * 8) * 2;

    #pragma unroll
    for (int k0 = 0; k0 < DIM; k0 += 16) {
        uint32_t af[4][4], bf[4][2];
        #pragma unroll
        for (int mt = 0; mt < 4; mt++)
            ldmatrix_x4(af[mt][0], af[mt][1], af[mt][2], af[mt][3],
                        a_base + (mt * 16 * ASTR + k0) * 2);
        #pragma unroll
        for (int nt = 0; nt < 4; nt++)
            ldmatrix_x2(bf[nt][0], bf[nt][1],
                        b_base + (nt * 8 * ASTR + k0) * 2);
        #pragma unroll
        for (int mt = 0; mt < 4; mt++)
            #pragma unroll
            for (int nt = 0; nt < 4; nt++)
                mma_bf16(acc[mt][nt], af[mt], bf[nt]);
    }
    __syncthreads();

    __nv_bfloat16*  stage = (__nv_bfloat16*)sm;
    unsigned short* st2   = (unsigned short*)(sm + 34816);
    bool mir = (tm != tn);

    #pragma unroll
    for (int mt = 0; mt < 4; mt++) {
        int r0 = wm * 64 + mt * 16 + (lane >> 2);
        #pragma unroll
        for (int nt = 0; nt < 4; nt++) {
            int c0 = wn * 32 + nt * 8 + (lane & 3) * 2;
            unsigned p0 = pack_bf16x2(acc[mt][nt][0], acc[mt][nt][1]);
            unsigned p1 = pack_bf16x2(acc[mt][nt][2], acc[mt][nt][3]);
            *(unsigned*)&stage[r0 * ASTR + c0]       = p0;
            *(unsigned*)&stage[(r0 + 8) * ASTR + c0] = p1;
            if (mir) {
                int ra = r0, rb = r0 + 8;
                st2[(c0)     * 128 + (((ra >> 3) ^ (c0 & 15)) * 8)       + (ra & 7)] = (unsigned short)(p0 & 0xFFFF);
                st2[(c0 + 1) * 128 + (((ra >> 3) ^ ((c0 + 1) & 15)) * 8) + (ra & 7)] = (unsigned short)(p0 >> 16);
                st2[(c0)     * 128 + (((rb >> 3) ^ (c0 & 15)) * 8)       + (rb & 7)] = (unsigned short)(p1 & 0xFFFF);
                st2[(c0 + 1) * 128 + (((rb >> 3) ^ ((c0 + 1) & 15)) * 8) + (rb & 7)] = (unsigned short)(p1 >> 16);
            }
        }
    }
    __syncthreads();
    if (!mir && tid < 128) stage[tid * ASTR + tid] = __float2bfloat16(-1e9f);
    __syncthreads();

    #pragma unroll
    for (int it = 0; it < 8; it++) {
        int i = tid + it * 256;
        int row = i >> 4, g = i & 15;
        uint4 v = *(uint4*)&stage[row * ASTR + g * 8];
        ((uint4*)(g_Sb + (size_t)(tm * 128 + row) * BN + tn * 128))[g] = v;
    }
    if (mir) {
        #pragma unroll
        for (int it = 0; it < 8; it++) {
            int i = tid + it * 256;
            int crow = i >> 4, g = i & 15;
            int pg = g ^ (crow & 15);
            uint4 v = *(uint4*)&st2[crow * 128 + pg * 8];
            ((uint4*)(g_Sb + (size_t)(tn * 128 + crow) * BN + tm * 128))[g] = v;
        }
    }
}

// ============================ per-row top-K + same-label sums ============================
__global__ void __launch_bounds__(NTH) topk_kernel() {
    __shared__ unsigned       sval[BN / 2];           // 16 KB
    __shared__ unsigned       hist[NBKT];             // 4 KB (low 256 reused by radix)
    __shared__ unsigned char  lab[BN];                // 8 KB
    __shared__ unsigned short wcand[NWARP][WSLOT];    // 1.5 KB
    __shared__ int            wcnt[NWARP];
    __shared__ float          wredA[NWARP], wredB[NWARP];
    __shared__ int            s_bsel, s_above, s_sel2, s_above2;

    int r    = blockIdx.x;
    int tid  = threadIdx.x;
    int lane = tid & 31;
    int w    = tid >> 5;

    for (int i = tid; i < NBKT; i += NTH) hist[i] = 0;
    for (int i = tid * 4; i < BN; i += NTH * 4) *(uchar4*)&lab[i] = *(const uchar4*)&g_lab[i];
    unsigned char myl = g_lab[r];
    __syncthreads();
    if (tid == 0) lab[r] = 0xFF;                       // sentinel (labels < 200)
    __syncthreads();

    unsigned mylw = (unsigned)myl * 0x01010101u;
    float ssum = 0.f;

    // ---- pass 1: streaming load + linear-value histogram + same-label sum ----
    const uint4* S4 = (const uint4*)(g_Sb + (size_t)r * BN);
    #pragma unroll
    for (int it = 0; it < 2; it++) {
        int i4 = tid + it * NTH;
        uint4 v = __ldcs(&S4[i4]);
        ((uint4*)sval)[i4] = v;
        int j0 = i4 * 8;
        unsigned e0 = __vcmpeq4(*(const unsigned*)&lab[j0],     mylw);
        unsigned e1 = __vcmpeq4(*(const unsigned*)&lab[j0 + 4], mylw);
        unsigned ws[4] = {v.x, v.y, v.z, v.w};
        unsigned es[4] = {e0 & 0xFFFFu, e0 >> 16, e1 & 0xFFFFu, e1 >> 16};
        #pragma unroll
        for (int c = 0; c < 4; c++) {
            float flo = __uint_as_float(ws[c] << 16);
            float fhi = __uint_as_float(ws[c] & 0xFFFF0000u);
            atomicAdd(&hist[bucket_of(flo)], 1u);
            atomicAdd(&hist[bucket_of(fhi)], 1u);
            if (es[c] & 0x00FFu) ssum += flo;
            if (es[c] & 0xFF00u) ssum += fhi;
        }
    }
    __syncthreads();

    if (tid < 32) warp_suffix_select(hist, NBKT, TOPK, &s_bsel, &s_above, lane);
    if (tid < NWARP + 32 && tid >= 32) wcnt[tid - 32] = 0;
    __syncthreads();
    int bsel = s_bsel;

    // ---- pass 2: above-bucket sum + warp-ballot candidate compaction ----
    float tsum = 0.f;
    int cnt = 0;
    #pragma unroll
    for (int it = 0; it < 8; it++) {
        int i = tid + it * NTH;
        unsigned x = sval[i];
        float flo = __uint_as_float(x << 16);
        float fhi = __uint_as_float(x & 0xFFFF0000u);
        int blo = bucket_of(flo), bhi = bucket_of(fhi);
        if (blo > bsel) tsum += flo;
        if (bhi > bsel) tsum += fhi;
        unsigned mlo = __ballot_sync(0xffffffffu, blo == bsel);
        if (blo == bsel) {
            int p = cnt + __popc(mlo & ((1u << lane) - 1u));
            if (p < WSLOT) wcand[w][p] = (unsigned short)fkey16(x & 0xFFFFu);
        }
        cnt += __popc(mlo);
        unsigned mhi = __ballot_sync(0xffffffffu, bhi == bsel);
        if (bhi == bsel) {
            int p = cnt + __popc(mhi & ((1u << lane) - 1u));
            if (p < WSLOT) wcand[w][p] = (unsigned short)fkey16(x >> 16);
        }
        cnt += __popc(mhi);
    }
    if (lane == 0) wcnt[w] = min(cnt, WSLOT);
    __syncthreads();
    int mycnt = wcnt[w];

    // ---- 2-pass radix over warp lists -> exact key of rem-th largest in bucket ----
    unsigned pref = 0, pmask = 0;
    int rem = TOPK - s_above;
    #pragma unroll
    for (int shift = 8; shift >= 0; shift -= 8) {
        for (int i = tid; i < 256; i += NTH) hist[i] = 0;
        __syncthreads();
        for (int t = lane; t < mycnt; t += 32) {
            unsigned k = wcand[w][t];
            if ((k & pmask) == pref) atomicAdd(&hist[(k >> shift) & 255u], 1u);
        }
        __syncthreads();
        if (tid < 32) warp_suffix_select(hist, 256, rem, &s_sel2, &s_above2, lane);
        __syncthreads();
        pref  |= ((unsigned)s_sel2) << shift;
        pmask |= 0xFFu << shift;
        rem   -= s_above2;
        __syncthreads();
    }

    // ---- strictly-above-threshold in-bucket sum from warp lists (deterministic) ----
    float gsum = 0.f;
    for (int t = lane; t < mycnt; t += 32)
        if ((unsigned)wcand[w][t] > pref) gsum += val16(wcand[w][t]);

    // ---- fixed-tree reduction ----
    float A = tsum + gsum, B = ssum;
    #pragma unroll
    for (int o = 16; o; o >>= 1) {
        A += __shfl_xor_sync(0xffffffffu, A, o);
        B += __shfl_xor_sync(0xffffffffu, B, o);
    }
    if (lane == 0) { wredA[w] = A; wredB[w] = B; }
    __syncthreads();
    if (tid == 0) {
        float At = 0.f, Bt = 0.f;
        #pragma unroll
        for (int ww = 0; ww < NWARP; ww++) { At += wredA[ww]; Bt += wredB[ww]; }
        g_partial[r] = At + (float)rem * val16(pref) - Bt;
    }
}

// ============================ final scalar reduce ============================
__global__ void reduce_kernel(float* __restrict__ out) {
    __shared__ double red[256];
    int tid = threadIdx.x;
    double s = 0.0;
    for (int i = tid; i < BN; i += 256) s += (double)g_partial[i];
    red[tid] = s;
    __syncthreads();
    for (int st = 128; st > 0; st >>= 1) {
        if (tid < st) red[tid] += red[tid + st];
        __syncthreads();
    }
    if (tid == 0) out[0] = (float)(red[0] / (double)BN);
}

// ============================ launch ============================
extern "C" void kernel_launch(void* const* d_in, const int* in_sizes, int n_in,
                              void* d_out, int out_size) {
    (void)in_sizes; (void)n_in; (void)out_size;
    const float*        feats = (const float*)d_in[0];
    const unsigned int* labw  = (const unsigned int*)d_in[1];
    float*              out   = (float*)d_out;

    const int smem = 2 * 128 * ASTR * 2;   // 69632 B
    cudaFuncSetAttribute(gemm_mma_kernel, cudaFuncAttributeMaxDynamicSharedMemorySize, smem);

    normalize_kernel<<<BN / 8, 256>>>(feats);
    label_kernel<<<1, 256>>>(labw);
    dim3 g(BN / 128, BN / 128);
    gemm_mma_kernel<<<g, 256, smem>>>();
    topk_kernel<<<BN, NTH>>>();
    reduce_kernel<<<1, 256>>>(out);
}

// round 8
// speedup vs baseline: 4.6772x; 1.3806x over previous
#include <cuda_runtime.h>
#include <cuda_bf16.h>
#include <cstdint>

#define BN    8192
#define DIM   128
#define TOPK  128
#define NTH   512
#define NWARP (NTH / 32)
#define WCAP  128
#define K0KEY 0xBE00u     // fkey16 of bf16(+0.125)
#define ASTR  136

// -------- device scratch --------
__device__ __nv_bfloat16 g_fnb[(size_t)BN * DIM];
__device__ __nv_bfloat16 g_Sb[(size_t)BN * BN];    // bf16 Gram (128 MB)
__device__ unsigned char g_lab[BN];
__device__ float         g_partial[BN];

// ============================ helpers ============================
__device__ __forceinline__ uint32_t smem_u32(const void* p) {
    uint32_t a;
    asm("{ .reg .u64 t; cvta.to.shared.u64 t, %1; cvt.u32.u64 %0, t; }" : "=r"(a) : "l"(p));
    return a;
}
__device__ __forceinline__ unsigned pack_bf16x2(float lo, float hi) {
    unsigned r;
    asm("cvt.rn.bf16x2.f32 %0, %1, %2;" : "=r"(r) : "f"(hi), "f"(lo));
    return r;
}
__device__ __forceinline__ void ldmatrix_x4(uint32_t& r0, uint32_t& r1, uint32_t& r2, uint32_t& r3, uint32_t a) {
    asm volatile("ldmatrix.sync.aligned.m8n8.x4.shared.b16 {%0,%1,%2,%3}, [%4];"
                 : "=r"(r0), "=r"(r1), "=r"(r2), "=r"(r3) : "r"(a));
}
__device__ __forceinline__ void ldmatrix_x2(uint32_t& r0, uint32_t& r1, uint32_t a) {
    asm volatile("ldmatrix.sync.aligned.m8n8.x2.shared.b16 {%0,%1}, [%2];"
                 : "=r"(r0), "=r"(r1) : "r"(a));
}
__device__ __forceinline__ void mma_bf16(float* d, const uint32_t* a, const uint32_t* b) {
    asm volatile(
        "mma.sync.aligned.m16n8k16.row.col.f32.bf16.bf16.f32 "
        "{%0,%1,%2,%3}, {%4,%5,%6,%7}, {%8,%9}, {%0,%1,%2,%3};"
        : "+f"(d[0]), "+f"(d[1]), "+f"(d[2]), "+f"(d[3])
        : "r"(a[0]), "r"(a[1]), "r"(a[2]), "r"(a[3]), "r"(b[0]), "r"(b[1]));
}

// 16-bit monotone key for bf16 bit patterns
__device__ __forceinline__ unsigned fkey16(unsigned x) {
    return (x ^ (0x8000u | (0x7FFFu & (0u - (x >> 15))))) & 0xFFFFu;
}
__device__ __forceinline__ float val16(unsigned k) {
    unsigned b = (k & 0x8000u) ? (k ^ 0x8000u) : ((~k) & 0xFFFFu);
    return __uint_as_float(b << 16);
}

__device__ __forceinline__ void warp_suffix_select(const unsigned* h, int nb, int target,
                                                   int* out_sel, int* out_above, int lane) {
    int ch = nb >> 5;
    int hi = nb - 1 - lane * ch;
    unsigned pc = 0;
    for (int t = 0; t < ch; t++) pc += h[hi - t];
    unsigned inc = pc;
    #pragma unroll
    for (int off = 1; off < 32; off <<= 1) {
        unsigned u = __shfl_up_sync(0xffffffffu, inc, off);
        if (lane >= off) inc += u;
    }
    unsigned exc = inc - pc;
    if (exc < (unsigned)target && inc >= (unsigned)target) {
        unsigned cum = exc;
        for (int t = 0; t < ch; t++) {
            unsigned c = h[hi - t];
            if (cum + c >= (unsigned)target) { *out_sel = hi - t; *out_above = (int)cum; break; }
            cum += c;
        }
    }
}

// ============================ normalize -> bf16 ============================
__global__ void normalize_kernel(const float* __restrict__ feats) {
    int w    = (blockIdx.x * blockDim.x + threadIdx.x) >> 5;
    int lane = threadIdx.x & 31;
    if (w >= BN) return;
    float4 v = ((const float4*)(feats + (size_t)w * DIM))[lane];
    float ss = v.x * v.x + v.y * v.y + v.z * v.z + v.w * v.w;
    #pragma unroll
    for (int o = 16; o; o >>= 1) ss += __shfl_xor_sync(0xffffffffu, ss, o);
    float inv = rsqrtf(ss);
    unsigned* dst = (unsigned*)(g_fnb + (size_t)w * DIM);
    dst[lane * 2 + 0] = pack_bf16x2(v.x * inv, v.y * inv);
    dst[lane * 2 + 1] = pack_bf16x2(v.z * inv, v.w * inv);
}

// ============================ labels -> u8 ============================
__global__ void label_kernel(const unsigned int* __restrict__ words) {
    int tid = threadIdx.x;
    int any = 0;
    for (int i = tid; i < BN / 2; i += blockDim.x) any |= (words[2 * i + 1] != 0u);
    int tot  = __syncthreads_or(any);
    int is64 = (tot == 0);
    for (int i = tid; i < BN; i += blockDim.x)
        g_lab[i] = (unsigned char)(is64 ? words[2 * i] : words[i]);
}

// ============================ bf16 mma.sync symmetric Gram GEMM ============================
__global__ void __launch_bounds__(256, 2) gemm_mma_kernel() {
    int tm = blockIdx.x, tn = blockIdx.y;
    if (tn < tm) return;

    extern __shared__ __align__(16) char sm[];
    __nv_bfloat16* Asm = (__nv_bfloat16*)sm;
    __nv_bfloat16* Bsm = (tm == tn) ? Asm : (__nv_bfloat16*)(sm + 128 * ASTR * 2);

    int tid  = threadIdx.x;
    int wid  = tid >> 5, lane = tid & 31;
    int wm   = wid >> 2, wn = wid & 3;

    const uint4* F = (const uint4*)g_fnb;
    #pragma unroll
    for (int it = 0; it < 8; it++) {
        int i = tid + it * 256;
        int r = i >> 4, g = i & 15;
        *(uint4*)(Asm + r * ASTR + g * 8) = F[(size_t)(tm * 128 + r) * 16 + g];
    }
    if (tm != tn) {
        #pragma unroll
        for (int it = 0; it < 8; it++) {
            int i = tid + it * 256;
            int r = i >> 4, g = i & 15;
            *(uint4*)(Bsm + r * ASTR + g * 8) = F[(size_t)(tn * 128 + r) * 16 + g];
        }
    }
    __syncthreads();

    float acc[4][4][4];
    #pragma unroll
    for (int i = 0; i < 4; i++)
        #pragma unroll
        for (int j = 0; j < 4; j++)
            #pragma unroll
            for (int c = 0; c < 4; c++) acc[i][j][c] = 0.f;

    uint32_t a_base = smem_u32(Asm) + ((wm * 64 + (lane & 15)) * ASTR + (lane >> 4) * 8) * 2;
    uint32_t b_base = smem_u32(Bsm) + ((wn * 32 + (lane & 7)) * ASTR + ((lane >> 3) & 1) * 8) * 2;

    #pragma unroll
    for (int k0 = 0; k0 < DIM; k0 += 16) {
        uint32_t af[4][4], bf[4][2];
        #pragma unroll
        for (int mt = 0; mt < 4; mt++)
            ldmatrix_x4(af[mt][0], af[mt][1], af[mt][2], af[mt][3],
                        a_base + (mt * 16 * ASTR + k0) * 2);
        #pragma unroll
        for (int nt = 0; nt < 4; nt++)
            ldmatrix_x2(bf[nt][0], bf[nt][1],
                        b_base + (nt * 8 * ASTR + k0) * 2);
        #pragma unroll
        for (int mt = 0; mt < 4; mt++)
            #pragma unroll
            for (int nt = 0; nt < 4; nt++)
                mma_bf16(acc[mt][nt], af[mt], bf[nt]);
    }
    __syncthreads();

    __nv_bfloat16*  stage = (__nv_bfloat16*)sm;
    unsigned short* st2   = (unsigned short*)(sm + 34816);
    bool mir = (tm != tn);

    #pragma unroll
    for (int mt = 0; mt < 4; mt++) {
        int r0 = wm * 64 + mt * 16 + (lane >> 2);
        #pragma unroll
        for (int nt = 0; nt < 4; nt++) {
            int c0 = wn * 32 + nt * 8 + (lane & 3) * 2;
            unsigned p0 = pack_bf16x2(acc[mt][nt][0], acc[mt][nt][1]);
            unsigned p1 = pack_bf16x2(acc[mt][nt][2], acc[mt][nt][3]);
            *(unsigned*)&stage[r0 * ASTR + c0]       = p0;
            *(unsigned*)&stage[(r0 + 8) * ASTR + c0] = p1;
            if (mir) {
                int ra = r0, rb = r0 + 8;
                st2[(c0)     * 128 + (((ra >> 3) ^ (c0 & 15)) * 8)       + (ra & 7)] = (unsigned short)(p0 & 0xFFFF);
                st2[(c0 + 1) * 128 + (((ra >> 3) ^ ((c0 + 1) & 15)) * 8) + (ra & 7)] = (unsigned short)(p0 >> 16);
                st2[(c0)     * 128 + (((rb >> 3) ^ (c0 & 15)) * 8)       + (rb & 7)] = (unsigned short)(p1 & 0xFFFF);
                st2[(c0 + 1) * 128 + (((rb >> 3) ^ ((c0 + 1) & 15)) * 8) + (rb & 7)] = (unsigned short)(p1 >> 16);
            }
        }
    }
    __syncthreads();
    if (!mir && tid < 128) stage[tid * ASTR + tid] = __float2bfloat16(-1e9f);
    __syncthreads();

    #pragma unroll
    for (int it = 0; it < 8; it++) {
        int i = tid + it * 256;
        int row = i >> 4, g = i & 15;
        uint4 v = *(uint4*)&stage[row * ASTR + g * 8];
        ((uint4*)(g_Sb + (size_t)(tm * 128 + row) * BN + tn * 128))[g] = v;
    }
    if (mir) {
        #pragma unroll
        for (int it = 0; it < 8; it++) {
            int i = tid + it * 256;
            int crow = i >> 4, g = i & 15;
            int pg = g ^ (crow & 15);
            uint4 v = *(uint4*)&st2[crow * 128 + pg * 8];
            ((uint4*)(g_Sb + (size_t)(tn * 128 + crow) * BN + tm * 128))[g] = v;
        }
    }
}

// ============================ per-row top-K + same-label sums ============================
// Fast path: only keys > K0KEY (~650/row) enter per-warp lists; radix-select runs on
// lists alone (exact: every key above any selected bucket is > K0KEY, hence in-list,
// given H >= TOPK which is verified). Fallback full-scan path keeps correctness for
// arbitrary inputs.
__global__ void __launch_bounds__(NTH, 3) topk_kernel() {
    __shared__ unsigned       sval[BN / 2];          // 16 KB raw bf16 pairs
    __shared__ unsigned       hist[256];             // 1 KB radix hist
    __shared__ unsigned short wcand[NWARP][WCAP];    // 4 KB per-warp high-key lists
    __shared__ int            wcnt[NWARP];
    __shared__ float          wredA[NWARP], wredB[NWARP];
    __shared__ int            s_sel, s_above, s_fast;

    int r    = blockIdx.x;
    int tid  = threadIdx.x;
    int lane = tid & 31;
    int w    = tid >> 5;

    unsigned char myl = g_lab[r];
    unsigned mylw = (unsigned)myl * 0x01010101u;
    const uint4*    S4 = (const uint4*)(g_Sb + (size_t)r * BN);
    const unsigned* LW = (const unsigned*)g_lab;

    // ---- pass 1: stream row, same-label sum, count high keys ----
    float ssum = 0.f;
    int cnt = 0;
    #pragma unroll
    for (int it = 0; it < 2; it++) {
        int i4 = tid + it * NTH;
        uint4 v = __ldcs(&S4[i4]);
        ((uint4*)sval)[i4] = v;
        int j0 = i4 * 8;
        unsigned e0 = __vcmpeq4(__ldg(&LW[i4 * 2]),     mylw);
        unsigned e1 = __vcmpeq4(__ldg(&LW[i4 * 2 + 1]), mylw);
        unsigned d = (unsigned)(r - j0);                 // self-exclusion
        if (d < 4u)      e0 &= ~(0xFFu << (d * 8));
        else if (d < 8u) e1 &= ~(0xFFu << ((d - 4) * 8));
        unsigned ws[4] = {v.x, v.y, v.z, v.w};
        unsigned es[4] = {e0 & 0xFFFFu, e0 >> 16, e1 & 0xFFFFu, e1 >> 16};
        #pragma unroll
        for (int c = 0; c < 4; c++) {
            unsigned klo = fkey16(ws[c] & 0xFFFFu), khi = fkey16(ws[c] >> 16);
            cnt += (klo > K0KEY) + (khi > K0KEY);
            if (es[c] & 0x00FFu) ssum += __uint_as_float(ws[c] << 16);
            if (es[c] & 0xFF00u) ssum += __uint_as_float(ws[c] & 0xFFFF0000u);
        }
    }

    // ---- warp exclusive scan of counts; write own keys (deterministic order) ----
    int incl = cnt;
    #pragma unroll
    for (int off = 1; off < 32; off <<= 1) {
        int u = __shfl_up_sync(0xffffffffu, incl, off);
        if (lane >= off) incl += u;
    }
    int wtotal = __shfl_sync(0xffffffffu, incl, 31);
    int pos = incl - cnt;
    if (wtotal <= WCAP && cnt) {
        #pragma unroll
        for (int it = 0; it < 2; it++) {
            int i4 = tid + it * NTH;
            uint4 v = ((uint4*)sval)[i4];
            unsigned ws2[4] = {v.x, v.y, v.z, v.w};
            #pragma unroll
            for (int c = 0; c < 4; c++) {
                unsigned klo = fkey16(ws2[c] & 0xFFFFu), khi = fkey16(ws2[c] >> 16);
                if (klo > K0KEY) wcand[w][pos++] = (unsigned short)klo;
                if (khi > K0KEY) wcand[w][pos++] = (unsigned short)khi;
            }
        }
    }
    if (lane == 31) wcnt[w] = wtotal;
    __syncthreads();

    if (tid < 32) {
        int c = (lane < NWARP) ? wcnt[lane] : 0;
        int mx = c, sum = c;
        #pragma unroll
        for (int off = 16; off; off >>= 1) {
            mx  = max(mx, __shfl_xor_sync(0xffffffffu, mx, off));
            sum += __shfl_xor_sync(0xffffffffu, sum, off);
        }
        if (lane == 0) s_fast = (mx <= WCAP && sum >= TOPK) ? 1 : 0;
    }
    __syncthreads();
    bool fast  = (s_fast != 0);
    int  mycnt = min(wcnt[w], WCAP);

    // ---- 2-pass 8-bit radix -> exact key of TOPK-th largest ----
    unsigned pref = 0, pmask = 0;
    int rem = TOPK;
    #pragma unroll
    for (int shift = 8; shift >= 0; shift -= 8) {
        if (tid < 256) hist[tid] = 0;
        __syncthreads();
        if (fast) {
            for (int t = lane; t < mycnt; t += 32) {
                unsigned k = wcand[w][t];
                if ((k & pmask) == pref) atomicAdd(&hist[(k >> shift) & 255u], 1u);
            }
        } else {
            #pragma unroll
            for (int it = 0; it < 8; it++) {
                unsigned x = sval[tid + it * NTH];
                unsigned klo = fkey16(x & 0xFFFFu), khi = fkey16(x >> 16);
                if ((klo & pmask) == pref) atomicAdd(&hist[(klo >> shift) & 255u], 1u);
                if ((khi & pmask) == pref) atomicAdd(&hist[(khi >> shift) & 255u], 1u);
            }
        }
        __syncthreads();
        if (tid < 32) warp_suffix_select(hist, 256, rem, &s_sel, &s_above, lane);
        __syncthreads();
        pref  |= ((unsigned)s_sel) << shift;
        pmask |= 0xFFu << shift;
        rem   -= s_above;
        __syncthreads();
    }

    // ---- top-K strict-above sum (deterministic order) ----
    float tsum = 0.f;
    if (fast) {
        for (int t = lane; t < mycnt; t += 32) {
            unsigned k = wcand[w][t];
            if (k > pref) tsum += val16(k);
        }
    } else {
        #pragma unroll
        for (int it = 0; it < 8; it++) {
            unsigned x = sval[tid + it * NTH];
            unsigned klo = fkey16(x & 0xFFFFu), khi = fkey16(x >> 16);
            if (klo > pref) tsum += val16(klo);
            if (khi > pref) tsum += val16(khi);
        }
    }

    // ---- fixed-tree reduction ----
    float A = tsum, B = ssum;
    #pragma unroll
    for (int o = 16; o; o >>= 1) {
        A += __shfl_xor_sync(0xffffffffu, A, o);
        B += __shfl_xor_sync(0xffffffffu, B, o);
    }
    if (lane == 0) { wredA[w] = A; wredB[w] = B; }
    __syncthreads();
    if (tid == 0) {
        float At = 0.f, Bt = 0.f;
        #pragma unroll
        for (int ww = 0; ww < NWARP; ww++) { At += wredA[ww]; Bt += wredB[ww]; }
        g_partial[r] = At + (float)rem * val16(pref) - Bt;
    }
}

// ============================ final scalar reduce ============================
__global__ void reduce_kernel(float* __restrict__ out) {
    __shared__ double red[256];
    int tid = threadIdx.x;
    double s = 0.0;
    for (int i = tid; i < BN; i += 256) s += (double)g_partial[i];
    red[tid] = s;
    __syncthreads();
    for (int st = 128; st > 0; st >>= 1) {
        if (tid < st) red[tid] += red[tid + st];
        __syncthreads();
    }
    if (tid == 0) out[0] = (float)(red[0] / (double)BN);
}

// ============================ launch ============================
extern "C" void kernel_launch(void* const* d_in, const int* in_sizes, int n_in,
                              void* d_out, int out_size) {
    (void)in_sizes; (void)n_in; (void)out_size;
    const float*        feats = (const float*)d_in[0];
    const unsigned int* labw  = (const unsigned int*)d_in[1];
    float*              out   = (float*)d_out;

    const int smem = 2 * 128 * ASTR * 2;   // 69632 B
    cudaFuncSetAttribute(gemm_mma_kernel, cudaFuncAttributeMaxDynamicSharedMemorySize, smem);

    normalize_kernel<<<BN / 8, 256>>>(feats);
    label_kernel<<<1, 256>>>(labw);
    dim3 g(BN / 128, BN / 128);
    gemm_mma_kernel<<<g, 256, smem>>>();
    topk_kernel<<<BN, NTH>>>();
    reduce_kernel<<<1, 256>>>(out);
}